// round 15
// baseline (speedup 1.0000x reference)
#include <cuda_runtime.h>
#include <math.h>
#include <stdint.h>

#define Bb   4
#define Nn   2048
#define FEAT 512
#define HIDD 512
#define Hh   8
#define HD   64
#define ROWS (Bb*Nn)          // 8192
#define BH   (Bb*Hh)          // 32

// ---------------- scratch (static device arrays; per-z doubled) ----------------
__device__ float g_q[(size_t)2*ROWS*HIDD];    // [z][BH,N,HD], q pre-scaled by log2e/8
__device__ float g_k[(size_t)2*ROWS*HIDD];
__device__ float g_v[(size_t)2*ROWS*HIDD];
__device__ float g_o[(size_t)2*ROWS*HIDD];    // [z][B,N,HID]
__device__ float g_msg[(size_t)2*ROWS*HIDD];
__device__ float g_h[(size_t)2*ROWS*2*FEAT];
__device__ float g_g[(size_t)2*ROWS*2*FEAT];
// transposed weights [N][K] (wqkvT rows are PERMUTED: j = (c%3)*512 + c/3)
__device__ float g_wqkvT[(size_t)(3*HIDD)*FEAT];
__device__ float g_wprojT[(size_t)HIDD*HIDD];
__device__ float g_w1T[(size_t)(2*FEAT)*(FEAT+HIDD)];
__device__ float g_w2T[(size_t)FEAT*(2*FEAT)];

// ---------------- helpers ----------------
__device__ __forceinline__ uint32_t s2u(const void* p) {
    return (uint32_t)__cvta_generic_to_shared(p);
}
__device__ __forceinline__ void cpa16(uint32_t dst, const void* src) {
    asm volatile("cp.async.cg.shared.global [%0], [%1], 16;\n" :: "r"(dst), "l"(src));
}
__device__ __forceinline__ void cpa_commit() {
    asm volatile("cp.async.commit_group;\n");
}
template<int N> __device__ __forceinline__ void cpa_wait() {
    asm volatile("cp.async.wait_group %0;\n" :: "n"(N));
}
__device__ __forceinline__ void ldsm_x4(uint32_t& r0, uint32_t& r1,
                                        uint32_t& r2, uint32_t& r3, uint32_t addr) {
    asm volatile("ldmatrix.sync.aligned.m8n8.x4.shared.b16 {%0,%1,%2,%3}, [%4];"
        : "=r"(r0), "=r"(r1), "=r"(r2), "=r"(r3) : "r"(addr));
}
__device__ __forceinline__ float ex2f(float x) {
    float r;
    asm("ex2.approx.f32 %0, %1;" : "=f"(r) : "f"(x));
    return r;
}

// mma on raw fp32 bits: tensor core truncates to tf32
__device__ __forceinline__ void mma_tf32(float* d,
    uint32_t a0, uint32_t a1, uint32_t a2, uint32_t a3,
    uint32_t b0, uint32_t b1)
{
    asm volatile(
        "mma.sync.aligned.m16n8k8.row.col.f32.tf32.tf32.f32 "
        "{%0,%1,%2,%3},{%4,%5,%6,%7},{%8,%9},{%0,%1,%2,%3};"
        : "+f"(d[0]), "+f"(d[1]), "+f"(d[2]), "+f"(d[3])
        : "r"(a0), "r"(a1), "r"(a2), "r"(a3), "r"(b0), "r"(b1));
}

// ---------------- merged weight transpose (qkv rows permuted) ----------------
__global__ __launch_bounds__(256) void trw_kernel(
    const float* __restrict__ s0, float* __restrict__ d0p,
    const float* __restrict__ s1, float* __restrict__ d1p,
    const float* __restrict__ s2, float* __restrict__ d2p,
    const float* __restrict__ s3, float* __restrict__ d3p)
{
    __shared__ float tile[32][33];
    int tb = blockIdx.x;
    const float* src; float* dst; int R, C, lt, perm;
    if (tb < 768)       { src=s0; dst=d0p; R=FEAT;      C=3*HIDD; lt=tb;      perm=1; }
    else if (tb < 1024) { src=s1; dst=d1p; R=HIDD;      C=HIDD;   lt=tb-768;  perm=0; }
    else if (tb < 2048) { src=s2; dst=d2p; R=FEAT+HIDD; C=2*FEAT; lt=tb-1024; perm=0; }
    else                { src=s3; dst=d3p; R=2*FEAT;    C=FEAT;   lt=tb-2048; perm=0; }
    int tC = C >> 5;
    int bx = lt % tC, by = lt / tC;

    int tx = threadIdx.x & 31, ty = threadIdx.x >> 5;
    int x = bx*32 + tx;
    #pragma unroll
    for (int i = ty; i < 32; i += 8) {
        int y = by*32 + i;
        tile[i][tx] = src[(size_t)y*C + x];
    }
    __syncthreads();
    int xt = by*32 + tx;
    #pragma unroll
    for (int i = ty; i < 32; i += 8) {
        int c = bx*32 + i;
        int jrow = perm ? ((c % 3)*512 + c/3) : c;
        dst[(size_t)jrow*R + xt] = tile[tx][i];
    }
}

// ---------------- batched tf32 GEMM over z=0,1; 3-stage cp.async + LDSM ----------------
#define GST_WORDS 5120
#define GSM_BYTES (3*GST_WORDS*4)   // 61440

__global__ __launch_bounds__(256, 2) void gemm_tf32(
    const float* __restrict__ A0, const float* __restrict__ A1, int lda,
    const float* __restrict__ A2_0, const float* __restrict__ A2_1, int lda2, int ksplit,
    const float* __restrict__ BT,
    const float* __restrict__ bias,
    const float* __restrict__ R0, const float* __restrict__ R1, int ldr,
    float* __restrict__ C, size_t zstrC, int ldc, int K)
{
    extern __shared__ uint32_t gsm[];

    const int z = blockIdx.z;
    const float* A     = z ? A1   : A0;
    const float* A2    = z ? A2_1 : A2_0;
    const float* resid = z ? R1   : R0;
    float* Cz = C + (size_t)z * zstrC;

    const int t    = threadIdx.x;
    const int lane = t & 31;
    const int warp = t >> 5;
    const int wm   = warp & 3;
    const int wn   = warp >> 2;
    const int rb   = blockIdx.y * 128;
    const int cb   = blockIdx.x * 128;

    const int arow = t >> 1;
    const int ah   = (t & 1) * 8;

    const int gid  = lane >> 2;
    const int tig  = lane & 3;

    const int a_r = ((lane >> 3) & 1)*8 + (lane & 7);
    const int a_c = (lane >> 4) * 4;
    const int b_r = (lane >> 4)*8 + (lane & 7);
    const int b_c = ((lane >> 3) & 1) * 4;

    const uint32_t smbase = s2u(gsm);

    auto issue_copy = [&](int kt, int s) {
        int kg = (kt << 4) + ah;
        const float* asrc = (A2 && kg >= ksplit)
            ? A2 + (size_t)(rb + arow) * lda2 + (kg - ksplit)
            : A  + (size_t)(rb + arow) * lda  + kg;
        uint32_t adst = smbase + (uint32_t)(s*GST_WORDS + arow*20 + ah) * 4;
        cpa16(adst,      asrc);
        cpa16(adst + 16, asrc + 4);
        const float* bsrc = BT + (size_t)(cb + arow) * K + kg;
        uint32_t bdst = smbase + (uint32_t)(s*GST_WORDS + 2560 + arow*20 + ah) * 4;
        cpa16(bdst,      bsrc);
        cpa16(bdst + 16, bsrc + 4);
        cpa_commit();
    };

    float acc[2][8][4] = {};

    const int nk = K >> 4;
    issue_copy(0, 0);
    if (nk > 1) issue_copy(1, 1);

    for (int kt = 0; kt < nk; ++kt) {
        const int s = kt % 3;
        if (kt < nk - 1) cpa_wait<1>(); else cpa_wait<0>();
        __syncthreads();
        if (kt + 2 < nk) issue_copy(kt + 2, (kt + 2) % 3);

        const uint32_t abase = smbase + (uint32_t)(s*GST_WORDS)*4;
        const uint32_t bbase = abase + 2560*4;
        #pragma unroll
        for (int ks = 0; ks < 2; ++ks) {
            uint32_t af0[4], af1[4];
            ldsm_x4(af0[0], af0[1], af0[2], af0[3],
                abase + (uint32_t)((wm*32 + a_r)*20 + ks*8 + a_c)*4);
            ldsm_x4(af1[0], af1[1], af1[2], af1[3],
                abase + (uint32_t)((wm*32 + 16 + a_r)*20 + ks*8 + a_c)*4);
            #pragma unroll
            for (int j = 0; j < 4; ++j) {
                uint32_t bf0, bf1, bf2, bf3;
                ldsm_x4(bf0, bf1, bf2, bf3,
                    bbase + (uint32_t)((wn*64 + j*16 + b_r)*20 + ks*8 + b_c)*4);
                mma_tf32(acc[0][2*j],   af0[0], af0[1], af0[2], af0[3], bf0, bf1);
                mma_tf32(acc[1][2*j],   af1[0], af1[1], af1[2], af1[3], bf0, bf1);
                mma_tf32(acc[0][2*j+1], af0[0], af0[1], af0[2], af0[3], bf2, bf3);
                mma_tf32(acc[1][2*j+1], af1[0], af1[1], af1[2], af1[3], bf2, bf3);
            }
        }
    }

    #pragma unroll
    for (int mt = 0; mt < 2; ++mt) {
        #pragma unroll
        for (int nt = 0; nt < 8; ++nt) {
            int row0 = rb + wm*32 + mt*16 + gid;
            int col  = cb + wn*64 + nt*8 + 2*tig;
            float2 bz = *(const float2*)(bias + col);
            float2 o0, o1;
            o0.x = acc[mt][nt][0] + bz.x;
            o0.y = acc[mt][nt][1] + bz.y;
            o1.x = acc[mt][nt][2] + bz.x;
            o1.y = acc[mt][nt][3] + bz.y;
            if (resid != nullptr) {
                float2 r0 = *(const float2*)(resid + (size_t)row0 * ldr + col);
                float2 r1 = *(const float2*)(resid + (size_t)(row0+8) * ldr + col);
                o0.x += r0.x; o0.y += r0.y;
                o1.x += r1.x; o1.y += r1.y;
            }
            *(float2*)(Cz + (size_t)row0 * ldc + col)     = o0;
            *(float2*)(Cz + (size_t)(row0+8) * ldc + col) = o1;
        }
    }
}

// ---------------- qkv GEMM with fused RoPE epilogue ----------------
__global__ __launch_bounds__(256, 2) void gemm_qkv(
    const float* __restrict__ A0, const float* __restrict__ A1,
    const float* __restrict__ BT,
    const float* __restrict__ bias,
    const float* __restrict__ enc0, const float* __restrict__ enc1,
    float* __restrict__ qb, float* __restrict__ kb, float* __restrict__ vb)
{
    extern __shared__ uint32_t gsm[];

    const int z = blockIdx.z;
    const float* A   = z ? A1   : A0;
    const float* enc = z ? enc1 : enc0;
    const size_t zo  = (size_t)z * ROWS * HIDD;

    const int t    = threadIdx.x;
    const int lane = t & 31;
    const int warp = t >> 5;
    const int wm   = warp & 3;
    const int wn   = warp >> 2;
    const int rb   = blockIdx.y * 128;
    const int cb   = blockIdx.x * 128;

    const int arow = t >> 1;
    const int ah   = (t & 1) * 8;

    const int gid  = lane >> 2;
    const int tig  = lane & 3;

    const int a_r = ((lane >> 3) & 1)*8 + (lane & 7);
    const int a_c = (lane >> 4) * 4;
    const int b_r = (lane >> 4)*8 + (lane & 7);
    const int b_c = ((lane >> 3) & 1) * 4;

    const uint32_t smbase = s2u(gsm);
    const int K = FEAT;

    auto issue_copy = [&](int kt, int s) {
        int kg = (kt << 4) + ah;
        const float* asrc = A + (size_t)(rb + arow) * FEAT + kg;
        uint32_t adst = smbase + (uint32_t)(s*GST_WORDS + arow*20 + ah) * 4;
        cpa16(adst,      asrc);
        cpa16(adst + 16, asrc + 4);
        const float* bsrc = BT + (size_t)(cb + arow) * K + kg;
        uint32_t bdst = smbase + (uint32_t)(s*GST_WORDS + 2560 + arow*20 + ah) * 4;
        cpa16(bdst,      bsrc);
        cpa16(bdst + 16, bsrc + 4);
        cpa_commit();
    };

    float acc[2][8][4] = {};

    const int nk = K >> 4;
    issue_copy(0, 0);
    issue_copy(1, 1);

    for (int kt = 0; kt < nk; ++kt) {
        const int s = kt % 3;
        if (kt < nk - 1) cpa_wait<1>(); else cpa_wait<0>();
        __syncthreads();
        if (kt + 2 < nk) issue_copy(kt + 2, (kt + 2) % 3);

        const uint32_t abase = smbase + (uint32_t)(s*GST_WORDS)*4;
        const uint32_t bbase = abase + 2560*4;
        #pragma unroll
        for (int ks = 0; ks < 2; ++ks) {
            uint32_t af0[4], af1[4];
            ldsm_x4(af0[0], af0[1], af0[2], af0[3],
                abase + (uint32_t)((wm*32 + a_r)*20 + ks*8 + a_c)*4);
            ldsm_x4(af1[0], af1[1], af1[2], af1[3],
                abase + (uint32_t)((wm*32 + 16 + a_r)*20 + ks*8 + a_c)*4);
            #pragma unroll
            for (int j = 0; j < 4; ++j) {
                uint32_t bf0, bf1, bf2, bf3;
                ldsm_x4(bf0, bf1, bf2, bf3,
                    bbase + (uint32_t)((wn*64 + j*16 + b_r)*20 + ks*8 + b_c)*4);
                mma_tf32(acc[0][2*j],   af0[0], af0[1], af0[2], af0[3], bf0, bf1);
                mma_tf32(acc[1][2*j],   af1[0], af1[1], af1[2], af1[3], bf0, bf1);
                mma_tf32(acc[0][2*j+1], af0[0], af0[1], af0[2], af0[3], bf2, bf3);
                mma_tf32(acc[1][2*j+1], af1[0], af1[1], af1[2], af1[3], bf2, bf3);
            }
        }
    }

    // fused RoPE epilogue
    const int sec = cb >> 9;
    const float QS = 0.125f * 1.44269504088896340736f;
    const size_t ESTR = (size_t)Bb * Nn * HD;
    float* dst = (sec == 0) ? qb : (sec == 1) ? kb : vb;

    #pragma unroll
    for (int mt = 0; mt < 2; ++mt) {
        #pragma unroll
        for (int nt = 0; nt < 8; ++nt) {
            int c    = cb + wn*64 + nt*8 + 2*tig;
            int tcol = c & 511;
            int h    = tcol >> 6;
            int hd   = tcol & 63;
            float bz0 = bias[h*192 + hd*3 + sec];
            float bz1 = bias[h*192 + (hd+1)*3 + sec];
            #pragma unroll
            for (int rr = 0; rr < 2; ++rr) {
                int row = rb + wm*32 + mt*16 + gid + rr*8;
                float v0 = acc[mt][nt][2*rr]   + bz0;
                float v1 = acc[mt][nt][2*rr+1] + bz1;
                float o0, o1;
                if (sec == 2) {
                    o0 = v0; o1 = v1;
                } else {
                    size_t eb = (size_t)row * HD + hd;
                    float f00 = enc[eb], f01 = enc[eb+1];
                    float f10 = enc[ESTR+eb], f11 = enc[ESTR+eb+1];
                    o0 = v0*f00 - v1*f10;
                    o1 = v1*f01 + v0*f11;
                    if (sec == 0) { o0 *= QS; o1 *= QS; }
                }
                int bb = row >> 11, n = row & 2047;
                *(float2*)&dst[zo + ((size_t)(bb*Hh + h)*Nn + n)*HD + hd] =
                    make_float2(o0, o1);
            }
        }
    }
}

// ---------------- tf32 flash attention: K and V both double-buffered, split waits ----------------
// smem words: QP[128][68] (Q staging -> P), K[2][64][68], V[2][64][72]
#define QPOFF 0
#define KOFF  (128*68)                 // 8704
#define KSTRIDE (64*68)                // 4352
#define VOFF  (KOFF + 2*KSTRIDE)       // 17408
#define VSTRIDE (64*72)                // 4608
#define FLASH_SMEM_U32 (VOFF + 2*VSTRIDE)  // 26624 words = 106496 B

__global__ __launch_bounds__(256, 2) void flash_tf32(
    const float* __restrict__ Q, const float* __restrict__ K,
    const float* __restrict__ V, float* __restrict__ O)
{
    extern __shared__ uint32_t smu[];
    float* Ps = (float*)(smu + QPOFF);

    const int z  = blockIdx.z;
    const int bh = blockIdx.y;
    const int b  = bh >> 3;
    const int h  = bh & 7;
    const size_t zo = (size_t)z * ROWS * HIDD;
    const float* Qg = Q + zo + (size_t)bh * Nn * HD;
    const float* Kg = K + zo + (size_t)bh * Nn * HD;
    const float* Vg = V + zo + (size_t)bh * Nn * HD;
    float* Og = O + zo;

    const int t    = threadIdx.x;
    const int lane = t & 31;
    const int warp = t >> 5;
    const int gid  = lane >> 2;
    const int tig  = lane & 3;
    const int q0r  = blockIdx.x * 128;

    const uint32_t qpa = s2u(smu + QPOFF);
    const uint32_t ksa = s2u(smu + KOFF);
    const uint32_t vsa = s2u(smu + VOFF);

    const int a_r = ((lane >> 3) & 1)*8 + (lane & 7);
    const int a_c = (lane >> 4) * 4;
    const int b_r = (lane >> 4)*8 + (lane & 7);
    const int b_c = ((lane >> 3) & 1) * 4;

    auto stage_k = [&](int j0, int s) {
        #pragma unroll
        for (int i = 0; i < 4; ++i) {
            int idx = t + 256*i;
            int row = idx >> 4, dq = (idx & 15) << 2;
            cpa16(ksa + (uint32_t)(s*KSTRIDE + row*68 + dq)*4,
                  Kg + (size_t)(j0 + row)*HD + dq);
        }
        cpa_commit();
    };
    auto stage_v = [&](int j0, int s) {
        #pragma unroll
        for (int i = 0; i < 4; ++i) {
            int idx = t + 256*i;
            int row = idx >> 4, dq = (idx & 15) << 2;
            cpa16(vsa + (uint32_t)(s*VSTRIDE + row*72 + dq)*4,
                  Vg + (size_t)(j0 + row)*HD + dq);
        }
        cpa_commit();
    };

    // prologue: stage Q (into QP), K(0), V(0)   [3 groups]
    #pragma unroll
    for (int i = 0; i < 8; ++i) {
        int idx = t + 256*i;
        int row = idx >> 4, dq = (idx & 15) << 2;
        cpa16(qpa + (uint32_t)(row*68 + dq)*4, Qg + (size_t)(q0r + row)*HD + dq);
    }
    cpa_commit();
    stage_k(0, 0);
    stage_v(0, 0);

    cpa_wait<2>();      // Q done (K0,V0 may fly)
    __syncthreads();

    // hoist Q fragments from QP (before P overwrites it)
    uint32_t qf[8][4];
    #pragma unroll
    for (int ks = 0; ks < 8; ++ks)
        ldsm_x4(qf[ks][0], qf[ks][1], qf[ks][2], qf[ks][3],
            qpa + (uint32_t)((warp*16 + a_r)*68 + ks*8 + a_c)*4);

    float accO[8][4] = {};
    float mrow[2] = {-1e30f, -1e30f};
    float lrow[2] = {0.f, 0.f};

    const int NT = Nn / 64;
    for (int it = 0; it < NT; ++it) {
        const int cur = it & 1;
        cpa_wait<1>();      // K(it) done; V(it) may still fly
        __syncthreads();    // K(it) visible; all warps fully done with tile it-1 buffers

        // prefetch K(it+1) into 1-cur (all warps done reading it at the barrier above)
        if (it + 1 < NT) stage_k((it+1)*64, 1-cur);

        // S = Q @ K^T
        const uint32_t kb_base = ksa + (uint32_t)(cur*KSTRIDE)*4;
        float s[8][4] = {};
        #pragma unroll
        for (int ks = 0; ks < 8; ++ks) {
            #pragma unroll
            for (int j = 0; j < 4; ++j) {
                uint32_t kf0, kf1, kf2, kf3;
                ldsm_x4(kf0, kf1, kf2, kf3,
                    kb_base + (uint32_t)((j*16 + b_r)*68 + ks*8 + b_c)*4);
                mma_tf32(s[2*j],   qf[ks][0], qf[ks][1], qf[ks][2], qf[ks][3], kf0, kf1);
                mma_tf32(s[2*j+1], qf[ks][0], qf[ks][1], qf[ks][2], qf[ks][3], kf2, kf3);
            }
        }

        // online softmax (log2 domain; q pre-scaled by log2e/8)
        #pragma unroll
        for (int g = 0; g < 2; ++g) {
            float tm = -1e30f;
            #pragma unroll
            for (int nt = 0; nt < 8; ++nt)
                tm = fmaxf(tm, fmaxf(s[nt][2*g], s[nt][2*g+1]));
            tm = fmaxf(tm, __shfl_xor_sync(0xffffffffu, tm, 1));
            tm = fmaxf(tm, __shfl_xor_sync(0xffffffffu, tm, 2));
            float mn = fmaxf(mrow[g], tm);
            float alpha = ex2f(mrow[g] - mn);
            mrow[g] = mn;
            float rs = 0.f;
            #pragma unroll
            for (int nt = 0; nt < 8; ++nt) {
                float p0 = ex2f(s[nt][2*g]   - mn);
                float p1 = ex2f(s[nt][2*g+1] - mn);
                s[nt][2*g] = p0; s[nt][2*g+1] = p1;
                rs += p0 + p1;
            }
            rs += __shfl_xor_sync(0xffffffffu, rs, 1);
            rs += __shfl_xor_sync(0xffffffffu, rs, 2);
            lrow[g] = lrow[g]*alpha + rs;
            #pragma unroll
            for (int nt = 0; nt < 8; ++nt) {
                accO[nt][2*g]   *= alpha;
                accO[nt][2*g+1] *= alpha;
            }
        }

        // store P (raw fp32) to this warp's rows of QP
        {
            int r0 = warp*16 + gid;
            #pragma unroll
            for (int nt = 0; nt < 8; ++nt) {
                int pc = nt*8 + 2*tig;
                *(float2*)&Ps[r0*68 + pc]     = make_float2(s[nt][0], s[nt][1]);
                *(float2*)&Ps[(r0+8)*68 + pc] = make_float2(s[nt][2], s[nt][3]);
            }
        }
        __syncwarp();

        // V(it) done; (K(it+1) may still fly at non-last iterations)
        if (it + 1 < NT) cpa_wait<1>(); else cpa_wait<0>();
        __syncthreads();    // V(it) visible to all warps

        // prefetch V(it+1) into 1-cur (all warps done with V[1-cur] since top barrier)
        if (it + 1 < NT) stage_v((it+1)*64, 1-cur);

        // O += P @ V (P frags via ldsm from QP; V scalar broadcast loads)
        const uint32_t* Vc = smu + VOFF + cur*VSTRIDE;
        #pragma unroll
        for (int ks = 0; ks < 8; ++ks) {
            uint32_t pf0, pf1, pf2, pf3;
            ldsm_x4(pf0, pf1, pf2, pf3,
                qpa + (uint32_t)((warp*16 + a_r)*68 + ks*8 + a_c)*4);
            #pragma unroll
            for (int nt = 0; nt < 8; ++nt) {
                int n = nt*8 + gid;
                int k = ks*8 + tig;
                uint32_t b0 = Vc[k*72 + n];
                uint32_t b1 = Vc[(k+4)*72 + n];
                mma_tf32(accO[nt], pf0, pf1, pf2, pf3, b0, b1);
            }
        }
    }

    #pragma unroll
    for (int g = 0; g < 2; ++g) {
        float inv = 1.0f / lrow[g];
        int n = q0r + warp*16 + gid + 8*g;
        #pragma unroll
        for (int nt = 0; nt < 8; ++nt) {
            int col = h*64 + nt*8 + 2*tig;
            float2 o;
            o.x = accO[nt][2*g]   * inv;
            o.y = accO[nt][2*g+1] * inv;
            *(float2*)&Og[((size_t)b * Nn + n) * HIDD + col] = o;
        }
    }
}

// ---------------- LayerNorm + exact GELU: single-pass stats, shuffle reductions ----------------
__global__ __launch_bounds__(256) void ln_gelu_kernel(
    const float* __restrict__ H, const float* __restrict__ g,
    const float* __restrict__ bta, float* __restrict__ out)
{
    __shared__ float part[8][2];
    __shared__ float stat[2];
    const size_t rowi = (size_t)blockIdx.y * ROWS + blockIdx.x;
    const float* p = H + rowi * (2*FEAT);
    int t = threadIdx.x;
    int lane = t & 31, warp = t >> 5;
    float4 v = ((const float4*)p)[t];

    float s1 = v.x + v.y + v.z + v.w;
    float s2 = v.x*v.x + v.y*v.y + v.z*v.z + v.w*v.w;
    #pragma unroll
    for (int m = 16; m > 0; m >>= 1) {
        s1 += __shfl_xor_sync(0xffffffffu, s1, m);
        s2 += __shfl_xor_sync(0xffffffffu, s2, m);
    }
    if (lane == 0) { part[warp][0] = s1; part[warp][1] = s2; }
    __syncthreads();
    if (warp == 0) {
        float a = (lane < 8) ? part[lane][0] : 0.f;
        float b = (lane < 8) ? part[lane][1] : 0.f;
        #pragma unroll
        for (int m = 4; m > 0; m >>= 1) {
            a += __shfl_xor_sync(0xffffffffu, a, m);
            b += __shfl_xor_sync(0xffffffffu, b, m);
        }
        if (lane == 0) {
            float mu  = a * (1.0f / (2*FEAT));
            float var = b * (1.0f / (2*FEAT)) - mu*mu;
            stat[0] = mu;
            stat[1] = rsqrtf(var + 1e-5f);
        }
    }
    __syncthreads();
    float mu = stat[0], rs = stat[1];

    int c = t << 2;
    float4 gv = *(const float4*)(g + c);
    float4 bv = *(const float4*)(bta + c);
    float y0 = (v.x - mu) * rs * gv.x + bv.x;
    float y1 = (v.y - mu) * rs * gv.y + bv.y;
    float y2 = (v.z - mu) * rs * gv.z + bv.z;
    float y3 = (v.w - mu) * rs * gv.w + bv.w;

    const float IS2 = 0.70710678118654752f;
    float4 o;
    o.x = 0.5f * y0 * (1.0f + erff(y0 * IS2));
    o.y = 0.5f * y1 * (1.0f + erff(y1 * IS2));
    o.z = 0.5f * y2 * (1.0f + erff(y2 * IS2));
    o.w = 0.5f * y3 * (1.0f + erff(y3 * IS2));
    ((float4*)(out + rowi * (2*FEAT)))[t] = o;
}

extern "C" void kernel_launch(void* const* d_in, const int* in_sizes, int n_in,
                              void* d_out, int out_size)
{
    const float* x0    = (const float*)d_in[0];
    const float* x1    = (const float*)d_in[1];
    const float* enc0  = (const float*)d_in[2];
    const float* enc1  = (const float*)d_in[3];
    const float* Wqkv  = (const float*)d_in[4];
    const float* bqkv  = (const float*)d_in[5];
    const float* Wproj = (const float*)d_in[6];
    const float* bproj = (const float*)d_in[7];
    const float* W1    = (const float*)d_in[8];
    const float* b1    = (const float*)d_in[9];
    const float* ln_g  = (const float*)d_in[10];
    const float* ln_b  = (const float*)d_in[11];
    const float* W2    = (const float*)d_in[12];
    const float* b2    = (const float*)d_in[13];
    float* out = (float*)d_out;

    float *q, *k, *v, *o, *msg, *hh, *gg;
    float *wqkvT, *wprojT, *w1T, *w2T;
    cudaGetSymbolAddress((void**)&q,   g_q);
    cudaGetSymbolAddress((void**)&k,   g_k);
    cudaGetSymbolAddress((void**)&v,   g_v);
    cudaGetSymbolAddress((void**)&o,   g_o);
    cudaGetSymbolAddress((void**)&msg, g_msg);
    cudaGetSymbolAddress((void**)&hh,  g_h);
    cudaGetSymbolAddress((void**)&gg,  g_g);
    cudaGetSymbolAddress((void**)&wqkvT,  g_wqkvT);
    cudaGetSymbolAddress((void**)&wprojT, g_wprojT);
    cudaGetSymbolAddress((void**)&w1T,    g_w1T);
    cudaGetSymbolAddress((void**)&w2T,    g_w2T);

    cudaFuncSetAttribute(gemm_tf32,
        cudaFuncAttributeMaxDynamicSharedMemorySize, GSM_BYTES);
    cudaFuncSetAttribute(gemm_qkv,
        cudaFuncAttributeMaxDynamicSharedMemorySize, GSM_BYTES);
    cudaFuncSetAttribute(flash_tf32,
        cudaFuncAttributeMaxDynamicSharedMemorySize, FLASH_SMEM_U32*4);

    // transpose all 4 weight matrices (qkv permuted) in one launch
    trw_kernel<<<2560, 256>>>(Wqkv, wqkvT, Wproj, wprojT, W1, w1T, W2, w2T);

    const size_t ZH   = (size_t)ROWS*HIDD;
    const size_t Z2F  = (size_t)ROWS*2*FEAT;

    // q/k/v = rope(x @ Wqkv + bqkv), fused epilogue
    gemm_qkv<<<dim3(3*HIDD/128, ROWS/128, 2), 256, GSM_BYTES>>>(
        x0, x1, wqkvT, bqkv, enc0, enc1, q, k, v);

    flash_tf32<<<dim3(Nn/128, BH, 2), 256, FLASH_SMEM_U32*4>>>(q, k, v, o);

    // message = O @ Wproj + bproj
    gemm_tf32<<<dim3(HIDD/128, ROWS/128, 2), 256, GSM_BYTES>>>(
        o, o + ZH, HIDD, nullptr, nullptr, 0, 1<<30,
        wprojT, bproj, nullptr, nullptr, 0,
        msg, ZH, HIDD, HIDD);

    // h = concat(x, msg) @ W1 + b1
    gemm_tf32<<<dim3(2*FEAT/128, ROWS/128, 2), 256, GSM_BYTES>>>(
        x0, x1, FEAT, msg, msg + ZH, HIDD, FEAT,
        w1T, b1, nullptr, nullptr, 0,
        hh, Z2F, 2*FEAT, FEAT + HIDD);

    ln_gelu_kernel<<<dim3(ROWS, 2), 256>>>(hh, ln_g, ln_b, gg);

    // out = x + g @ W2 + b2
    gemm_tf32<<<dim3(FEAT/128, ROWS/128, 2), 256, GSM_BYTES>>>(
        gg, gg + Z2F, 2*FEAT, nullptr, nullptr, 0, 1<<30,
        w2T, b2, x0, x1, FEAT,
        out, (size_t)ROWS*FEAT, FEAT, 2*FEAT);
}

// round 16
// speedup vs baseline: 1.1894x; 1.1894x over previous
#include <cuda_runtime.h>
#include <cuda_fp16.h>
#include <math.h>
#include <stdint.h>

#define Bb   4
#define Nn   2048
#define FEAT 512
#define HIDD 512
#define Hh   8
#define HD   64
#define ROWS (Bb*Nn)          // 8192
#define BH   (Bb*Hh)          // 32

// ---------------- scratch (static device arrays; per-z doubled) ----------------
__device__ __half g_q[(size_t)2*ROWS*HIDD];   // [z][BH,N,HD] halves, q pre-scaled log2e/8
__device__ __half g_k[(size_t)2*ROWS*HIDD];
__device__ __half g_v[(size_t)2*ROWS*HIDD];
__device__ float g_o[(size_t)2*ROWS*HIDD];    // [z][B,N,HID]
__device__ float g_msg[(size_t)2*ROWS*HIDD];
__device__ float g_h[(size_t)2*ROWS*2*FEAT];
__device__ float g_g[(size_t)2*ROWS*2*FEAT];
// transposed weights [N][K] (wqkvT rows are PERMUTED: j = (c%3)*512 + c/3)
__device__ float g_wqkvT[(size_t)(3*HIDD)*FEAT];
__device__ float g_wprojT[(size_t)HIDD*HIDD];
__device__ float g_w1T[(size_t)(2*FEAT)*(FEAT+HIDD)];
__device__ float g_w2T[(size_t)FEAT*(2*FEAT)];

// ---------------- helpers ----------------
__device__ __forceinline__ uint32_t s2u(const void* p) {
    return (uint32_t)__cvta_generic_to_shared(p);
}
__device__ __forceinline__ void cpa16(uint32_t dst, const void* src) {
    asm volatile("cp.async.cg.shared.global [%0], [%1], 16;\n" :: "r"(dst), "l"(src));
}
__device__ __forceinline__ void cpa_commit() {
    asm volatile("cp.async.commit_group;\n");
}
template<int N> __device__ __forceinline__ void cpa_wait() {
    asm volatile("cp.async.wait_group %0;\n" :: "n"(N));
}
__device__ __forceinline__ void ldsm_x4(uint32_t& r0, uint32_t& r1,
                                        uint32_t& r2, uint32_t& r3, uint32_t addr) {
    asm volatile("ldmatrix.sync.aligned.m8n8.x4.shared.b16 {%0,%1,%2,%3}, [%4];"
        : "=r"(r0), "=r"(r1), "=r"(r2), "=r"(r3) : "r"(addr));
}
__device__ __forceinline__ void ldsm_x4_t(uint32_t& r0, uint32_t& r1,
                                          uint32_t& r2, uint32_t& r3, uint32_t addr) {
    asm volatile("ldmatrix.sync.aligned.m8n8.x4.trans.shared.b16 {%0,%1,%2,%3}, [%4];"
        : "=r"(r0), "=r"(r1), "=r"(r2), "=r"(r3) : "r"(addr));
}
__device__ __forceinline__ float ex2f(float x) {
    float r;
    asm("ex2.approx.f32 %0, %1;" : "=f"(r) : "f"(x));
    return r;
}

// tf32 mma on raw fp32 bits (tensor core truncates)
__device__ __forceinline__ void mma_tf32(float* d,
    uint32_t a0, uint32_t a1, uint32_t a2, uint32_t a3,
    uint32_t b0, uint32_t b1)
{
    asm volatile(
        "mma.sync.aligned.m16n8k16.row.col.f32.f16.f16.f32 "
        "{%0,%1,%2,%3},{%4,%5,%6,%7},{%8,%9},{%0,%1,%2,%3};"
        : "+f"(d[0]), "+f"(d[1]), "+f"(d[2]), "+f"(d[3])
        : "r"(a0), "r"(a1), "r"(a2), "r"(a3), "r"(b0), "r"(b1));
}
// NOTE: the above name is used ONLY by flash (f16). Real tf32 mma below.
__device__ __forceinline__ void mma_t32(float* d,
    uint32_t a0, uint32_t a1, uint32_t a2, uint32_t a3,
    uint32_t b0, uint32_t b1)
{
    asm volatile(
        "mma.sync.aligned.m16n8k8.row.col.f32.tf32.tf32.f32 "
        "{%0,%1,%2,%3},{%4,%5,%6,%7},{%8,%9},{%0,%1,%2,%3};"
        : "+f"(d[0]), "+f"(d[1]), "+f"(d[2]), "+f"(d[3])
        : "r"(a0), "r"(a1), "r"(a2), "r"(a3), "r"(b0), "r"(b1));
}

// ---------------- merged weight transpose (qkv rows permuted) ----------------
__global__ __launch_bounds__(256) void trw_kernel(
    const float* __restrict__ s0, float* __restrict__ d0p,
    const float* __restrict__ s1, float* __restrict__ d1p,
    const float* __restrict__ s2, float* __restrict__ d2p,
    const float* __restrict__ s3, float* __restrict__ d3p)
{
    __shared__ float tile[32][33];
    int tb = blockIdx.x;
    const float* src; float* dst; int R, C, lt, perm;
    if (tb < 768)       { src=s0; dst=d0p; R=FEAT;      C=3*HIDD; lt=tb;      perm=1; }
    else if (tb < 1024) { src=s1; dst=d1p; R=HIDD;      C=HIDD;   lt=tb-768;  perm=0; }
    else if (tb < 2048) { src=s2; dst=d2p; R=FEAT+HIDD; C=2*FEAT; lt=tb-1024; perm=0; }
    else                { src=s3; dst=d3p; R=2*FEAT;    C=FEAT;   lt=tb-2048; perm=0; }
    int tC = C >> 5;
    int bx = lt % tC, by = lt / tC;

    int tx = threadIdx.x & 31, ty = threadIdx.x >> 5;
    int x = bx*32 + tx;
    #pragma unroll
    for (int i = ty; i < 32; i += 8) {
        int y = by*32 + i;
        tile[i][tx] = src[(size_t)y*C + x];
    }
    __syncthreads();
    int xt = by*32 + tx;
    #pragma unroll
    for (int i = ty; i < 32; i += 8) {
        int c = bx*32 + i;
        int jrow = perm ? ((c % 3)*512 + c/3) : c;
        dst[(size_t)jrow*R + xt] = tile[tx][i];
    }
}

// ---------------- batched tf32 GEMM over z=0,1; 3-stage cp.async + LDSM ----------------
#define GST_WORDS 5120
#define GSM_BYTES (3*GST_WORDS*4)   // 61440

__global__ __launch_bounds__(256, 2) void gemm_tf32(
    const float* __restrict__ A0, const float* __restrict__ A1, int lda,
    const float* __restrict__ A2_0, const float* __restrict__ A2_1, int lda2, int ksplit,
    const float* __restrict__ BT,
    const float* __restrict__ bias,
    const float* __restrict__ R0, const float* __restrict__ R1, int ldr,
    float* __restrict__ C, size_t zstrC, int ldc, int K)
{
    extern __shared__ uint32_t gsm[];

    const int z = blockIdx.z;
    const float* A     = z ? A1   : A0;
    const float* A2    = z ? A2_1 : A2_0;
    const float* resid = z ? R1   : R0;
    float* Cz = C + (size_t)z * zstrC;

    const int t    = threadIdx.x;
    const int lane = t & 31;
    const int warp = t >> 5;
    const int wm   = warp & 3;
    const int wn   = warp >> 2;
    const int rb   = blockIdx.y * 128;
    const int cb   = blockIdx.x * 128;

    const int arow = t >> 1;
    const int ah   = (t & 1) * 8;

    const int gid  = lane >> 2;
    const int tig  = lane & 3;

    const int a_r = ((lane >> 3) & 1)*8 + (lane & 7);
    const int a_c = (lane >> 4) * 4;
    const int b_r = (lane >> 4)*8 + (lane & 7);
    const int b_c = ((lane >> 3) & 1) * 4;

    const uint32_t smbase = s2u(gsm);

    auto issue_copy = [&](int kt, int s) {
        int kg = (kt << 4) + ah;
        const float* asrc = (A2 && kg >= ksplit)
            ? A2 + (size_t)(rb + arow) * lda2 + (kg - ksplit)
            : A  + (size_t)(rb + arow) * lda  + kg;
        uint32_t adst = smbase + (uint32_t)(s*GST_WORDS + arow*20 + ah) * 4;
        cpa16(adst,      asrc);
        cpa16(adst + 16, asrc + 4);
        const float* bsrc = BT + (size_t)(cb + arow) * K + kg;
        uint32_t bdst = smbase + (uint32_t)(s*GST_WORDS + 2560 + arow*20 + ah) * 4;
        cpa16(bdst,      bsrc);
        cpa16(bdst + 16, bsrc + 4);
        cpa_commit();
    };

    float acc[2][8][4] = {};

    const int nk = K >> 4;
    issue_copy(0, 0);
    if (nk > 1) issue_copy(1, 1);

    for (int kt = 0; kt < nk; ++kt) {
        const int s = kt % 3;
        if (kt < nk - 1) cpa_wait<1>(); else cpa_wait<0>();
        __syncthreads();
        if (kt + 2 < nk) issue_copy(kt + 2, (kt + 2) % 3);

        const uint32_t abase = smbase + (uint32_t)(s*GST_WORDS)*4;
        const uint32_t bbase = abase + 2560*4;
        #pragma unroll
        for (int ks = 0; ks < 2; ++ks) {
            uint32_t af0[4], af1[4];
            ldsm_x4(af0[0], af0[1], af0[2], af0[3],
                abase + (uint32_t)((wm*32 + a_r)*20 + ks*8 + a_c)*4);
            ldsm_x4(af1[0], af1[1], af1[2], af1[3],
                abase + (uint32_t)((wm*32 + 16 + a_r)*20 + ks*8 + a_c)*4);
            #pragma unroll
            for (int j = 0; j < 4; ++j) {
                uint32_t bf0, bf1, bf2, bf3;
                ldsm_x4(bf0, bf1, bf2, bf3,
                    bbase + (uint32_t)((wn*64 + j*16 + b_r)*20 + ks*8 + b_c)*4);
                mma_t32(acc[0][2*j],   af0[0], af0[1], af0[2], af0[3], bf0, bf1);
                mma_t32(acc[1][2*j],   af1[0], af1[1], af1[2], af1[3], bf0, bf1);
                mma_t32(acc[0][2*j+1], af0[0], af0[1], af0[2], af0[3], bf2, bf3);
                mma_t32(acc[1][2*j+1], af1[0], af1[1], af1[2], af1[3], bf2, bf3);
            }
        }
    }

    #pragma unroll
    for (int mt = 0; mt < 2; ++mt) {
        #pragma unroll
        for (int nt = 0; nt < 8; ++nt) {
            int row0 = rb + wm*32 + mt*16 + gid;
            int col  = cb + wn*64 + nt*8 + 2*tig;
            float2 bz = *(const float2*)(bias + col);
            float2 o0, o1;
            o0.x = acc[mt][nt][0] + bz.x;
            o0.y = acc[mt][nt][1] + bz.y;
            o1.x = acc[mt][nt][2] + bz.x;
            o1.y = acc[mt][nt][3] + bz.y;
            if (resid != nullptr) {
                float2 r0 = *(const float2*)(resid + (size_t)row0 * ldr + col);
                float2 r1 = *(const float2*)(resid + (size_t)(row0+8) * ldr + col);
                o0.x += r0.x; o0.y += r0.y;
                o1.x += r1.x; o1.y += r1.y;
            }
            *(float2*)(Cz + (size_t)row0 * ldc + col)     = o0;
            *(float2*)(Cz + (size_t)(row0+8) * ldc + col) = o1;
        }
    }
}

// ---------------- qkv GEMM with fused RoPE epilogue (emits half) ----------------
__global__ __launch_bounds__(256, 2) void gemm_qkv(
    const float* __restrict__ A0, const float* __restrict__ A1,
    const float* __restrict__ BT,
    const float* __restrict__ bias,
    const float* __restrict__ enc0, const float* __restrict__ enc1,
    __half* __restrict__ qb, __half* __restrict__ kb, __half* __restrict__ vb)
{
    extern __shared__ uint32_t gsm[];

    const int z = blockIdx.z;
    const float* A   = z ? A1   : A0;
    const float* enc = z ? enc1 : enc0;
    const size_t zo  = (size_t)z * ROWS * HIDD;

    const int t    = threadIdx.x;
    const int lane = t & 31;
    const int warp = t >> 5;
    const int wm   = warp & 3;
    const int wn   = warp >> 2;
    const int rb   = blockIdx.y * 128;
    const int cb   = blockIdx.x * 128;

    const int arow = t >> 1;
    const int ah   = (t & 1) * 8;

    const int gid  = lane >> 2;
    const int tig  = lane & 3;

    const int a_r = ((lane >> 3) & 1)*8 + (lane & 7);
    const int a_c = (lane >> 4) * 4;
    const int b_r = (lane >> 4)*8 + (lane & 7);
    const int b_c = ((lane >> 3) & 1) * 4;

    const uint32_t smbase = s2u(gsm);
    const int K = FEAT;

    auto issue_copy = [&](int kt, int s) {
        int kg = (kt << 4) + ah;
        const float* asrc = A + (size_t)(rb + arow) * FEAT + kg;
        uint32_t adst = smbase + (uint32_t)(s*GST_WORDS + arow*20 + ah) * 4;
        cpa16(adst,      asrc);
        cpa16(adst + 16, asrc + 4);
        const float* bsrc = BT + (size_t)(cb + arow) * K + kg;
        uint32_t bdst = smbase + (uint32_t)(s*GST_WORDS + 2560 + arow*20 + ah) * 4;
        cpa16(bdst,      bsrc);
        cpa16(bdst + 16, bsrc + 4);
        cpa_commit();
    };

    float acc[2][8][4] = {};

    const int nk = K >> 4;
    issue_copy(0, 0);
    issue_copy(1, 1);

    for (int kt = 0; kt < nk; ++kt) {
        const int s = kt % 3;
        if (kt < nk - 1) cpa_wait<1>(); else cpa_wait<0>();
        __syncthreads();
        if (kt + 2 < nk) issue_copy(kt + 2, (kt + 2) % 3);

        const uint32_t abase = smbase + (uint32_t)(s*GST_WORDS)*4;
        const uint32_t bbase = abase + 2560*4;
        #pragma unroll
        for (int ks = 0; ks < 2; ++ks) {
            uint32_t af0[4], af1[4];
            ldsm_x4(af0[0], af0[1], af0[2], af0[3],
                abase + (uint32_t)((wm*32 + a_r)*20 + ks*8 + a_c)*4);
            ldsm_x4(af1[0], af1[1], af1[2], af1[3],
                abase + (uint32_t)((wm*32 + 16 + a_r)*20 + ks*8 + a_c)*4);
            #pragma unroll
            for (int j = 0; j < 4; ++j) {
                uint32_t bf0, bf1, bf2, bf3;
                ldsm_x4(bf0, bf1, bf2, bf3,
                    bbase + (uint32_t)((wn*64 + j*16 + b_r)*20 + ks*8 + b_c)*4);
                mma_t32(acc[0][2*j],   af0[0], af0[1], af0[2], af0[3], bf0, bf1);
                mma_t32(acc[1][2*j],   af1[0], af1[1], af1[2], af1[3], bf0, bf1);
                mma_t32(acc[0][2*j+1], af0[0], af0[1], af0[2], af0[3], bf2, bf3);
                mma_t32(acc[1][2*j+1], af1[0], af1[1], af1[2], af1[3], bf2, bf3);
            }
        }
    }

    // fused RoPE epilogue -> half
    const int sec = cb >> 9;
    const float QS = 0.125f * 1.44269504088896340736f;
    const size_t ESTR = (size_t)Bb * Nn * HD;
    __half* dst = (sec == 0) ? qb : (sec == 1) ? kb : vb;

    #pragma unroll
    for (int mt = 0; mt < 2; ++mt) {
        #pragma unroll
        for (int nt = 0; nt < 8; ++nt) {
            int c    = cb + wn*64 + nt*8 + 2*tig;
            int tcol = c & 511;
            int h    = tcol >> 6;
            int hd   = tcol & 63;
            float bz0 = bias[h*192 + hd*3 + sec];
            float bz1 = bias[h*192 + (hd+1)*3 + sec];
            #pragma unroll
            for (int rr = 0; rr < 2; ++rr) {
                int row = rb + wm*32 + mt*16 + gid + rr*8;
                float v0 = acc[mt][nt][2*rr]   + bz0;
                float v1 = acc[mt][nt][2*rr+1] + bz1;
                float o0, o1;
                if (sec == 2) {
                    o0 = v0; o1 = v1;
                } else {
                    size_t eb = (size_t)row * HD + hd;
                    float f00 = enc[eb], f01 = enc[eb+1];
                    float f10 = enc[ESTR+eb], f11 = enc[ESTR+eb+1];
                    o0 = v0*f00 - v1*f10;
                    o1 = v1*f01 + v0*f11;
                    if (sec == 0) { o0 *= QS; o1 *= QS; }
                }
                int bb = row >> 11, n = row & 2047;
                *(__half2*)&dst[zo + ((size_t)(bb*Hh + h)*Nn + n)*HD + hd] =
                    __floats2half2_rn(o0, o1);
            }
        }
    }
}

// ---------------- fp16 flash attention: m16n8k16, K/V double-buffered ----------------
// smem halves pitch 72. Words: QP 128*36=4608 | K 2*2304 | V 2*2304
#define HP 72
#define QPW 0
#define KOFFW 4608
#define KSTRW 2304
#define VOFFW (KOFFW + 2*KSTRW)       // 9216
#define VSTRW 2304
#define FLASH_SMEM_B ((VOFFW + 2*VSTRW)*4)   // 55296

__global__ __launch_bounds__(256, 2) void flash_f16(
    const __half* __restrict__ Q, const __half* __restrict__ K,
    const __half* __restrict__ V, float* __restrict__ O)
{
    extern __shared__ uint32_t smu[];

    const int z  = blockIdx.z;
    const int bh = blockIdx.y;
    const int b  = bh >> 3;
    const int h  = bh & 7;
    const size_t zo = (size_t)z * ROWS * HIDD;
    const __half* Qg = Q + zo + (size_t)bh * Nn * HD;
    const __half* Kg = K + zo + (size_t)bh * Nn * HD;
    const __half* Vg = V + zo + (size_t)bh * Nn * HD;
    float* Og = O + zo;

    const int t    = threadIdx.x;
    const int lane = t & 31;
    const int warp = t >> 5;
    const int gid  = lane >> 2;
    const int tig  = lane & 3;
    const int q0r  = blockIdx.x * 128;

    const uint32_t smb = s2u(smu);

    // ldsm address components (A / P: 16x16 halves)
    const int lm  = lane & 15;             // row within 16
    const int ah8 = (lane >> 4) * 8;       // col half-offset
    // V trans ldsm components
    const int vrow = (lane & 7) + ((lane >> 3) & 1) * 8;
    const int vcol = (lane >> 4) * 8;

    auto stage_k = [&](int j0, int s) {
        #pragma unroll
        for (int i = 0; i < 2; ++i) {
            int idx = t + 256*i;
            int row = idx >> 3, ch = (idx & 7) * 8;
            cpa16(smb + (uint32_t)(KOFFW + s*KSTRW)*4 + (uint32_t)(row*HP + ch)*2,
                  Kg + (size_t)(j0 + row)*HD + ch);
        }
        cpa_commit();
    };
    auto stage_v = [&](int j0, int s) {
        #pragma unroll
        for (int i = 0; i < 2; ++i) {
            int idx = t + 256*i;
            int row = idx >> 3, ch = (idx & 7) * 8;
            cpa16(smb + (uint32_t)(VOFFW + s*VSTRW)*4 + (uint32_t)(row*HP + ch)*2,
                  Vg + (size_t)(j0 + row)*HD + ch);
        }
        cpa_commit();
    };

    // prologue: stage Q (into QP), K(0), V(0)
    #pragma unroll
    for (int i = 0; i < 4; ++i) {
        int idx = t + 256*i;
        int row = idx >> 3, ch = (idx & 7) * 8;
        cpa16(smb + (uint32_t)(row*HP + ch)*2, Qg + (size_t)(q0r + row)*HD + ch);
    }
    cpa_commit();
    stage_k(0, 0);
    stage_v(0, 0);

    cpa_wait<2>();
    __syncthreads();

    // hoist Q fragments (4 k-steps of 16)
    uint32_t qf[4][4];
    #pragma unroll
    for (int ks = 0; ks < 4; ++ks)
        ldsm_x4(qf[ks][0], qf[ks][1], qf[ks][2], qf[ks][3],
            smb + (uint32_t)((warp*16 + lm)*HP + ks*16 + ah8)*2);

    float accO[8][4] = {};
    float mrow[2] = {-1e30f, -1e30f};
    float lrow[2] = {0.f, 0.f};

    const int NT = Nn / 64;
    for (int it = 0; it < NT; ++it) {
        const int cur = it & 1;
        cpa_wait<1>();      // K(it) done
        __syncthreads();

        if (it + 1 < NT) stage_k((it+1)*64, 1-cur);

        // S = Q @ K^T : B loaded directly (contiguous k-halves in K [kv][d])
        const uint32_t* Kw = smu + KOFFW + cur*KSTRW;
        float s[8][4] = {};
        #pragma unroll
        for (int ks = 0; ks < 4; ++ks) {
            #pragma unroll
            for (int nt = 0; nt < 8; ++nt) {
                int n = nt*8 + gid;
                uint32_t b0 = Kw[n*36 + ks*8 + tig];
                uint32_t b1 = Kw[n*36 + ks*8 + tig + 4];
                mma_tf32(s[nt], qf[ks][0], qf[ks][1], qf[ks][2], qf[ks][3], b0, b1);
            }
        }

        // online softmax (log2 domain)
        #pragma unroll
        for (int g = 0; g < 2; ++g) {
            float tm = -1e30f;
            #pragma unroll
            for (int nt = 0; nt < 8; ++nt)
                tm = fmaxf(tm, fmaxf(s[nt][2*g], s[nt][2*g+1]));
            tm = fmaxf(tm, __shfl_xor_sync(0xffffffffu, tm, 1));
            tm = fmaxf(tm, __shfl_xor_sync(0xffffffffu, tm, 2));
            float mn = fmaxf(mrow[g], tm);
            float alpha = ex2f(mrow[g] - mn);
            mrow[g] = mn;
            float rs = 0.f;
            #pragma unroll
            for (int nt = 0; nt < 8; ++nt) {
                float p0 = ex2f(s[nt][2*g]   - mn);
                float p1 = ex2f(s[nt][2*g+1] - mn);
                s[nt][2*g] = p0; s[nt][2*g+1] = p1;
                rs += p0 + p1;
            }
            rs += __shfl_xor_sync(0xffffffffu, rs, 1);
            rs += __shfl_xor_sync(0xffffffffu, rs, 2);
            lrow[g] = lrow[g]*alpha + rs;
            #pragma unroll
            for (int nt = 0; nt < 8; ++nt) {
                accO[nt][2*g]   *= alpha;
                accO[nt][2*g+1] *= alpha;
            }
        }

        // store P as half2 into QP rows (per-warp rows only)
        {
            int r0 = warp*16 + gid;
            #pragma unroll
            for (int nt = 0; nt < 8; ++nt) {
                *(__half2*)&smu[r0*36 + nt*4 + tig] =
                    __floats2half2_rn(s[nt][0], s[nt][1]);
                *(__half2*)&smu[(r0+8)*36 + nt*4 + tig] =
                    __floats2half2_rn(s[nt][2], s[nt][3]);
            }
        }
        __syncwarp();

        if (it + 1 < NT) cpa_wait<1>(); else cpa_wait<0>();   // V(it) done
        __syncthreads();

        if (it + 1 < NT) stage_v((it+1)*64, 1-cur);

        // O += P @ V : P via ldsm.x4, V via ldsm.x4.trans on [kv][d]
        const uint32_t vbase = smb + (uint32_t)(VOFFW + cur*VSTRW)*4;
        #pragma unroll
        for (int ks = 0; ks < 4; ++ks) {
            uint32_t pf0, pf1, pf2, pf3;
            ldsm_x4(pf0, pf1, pf2, pf3,
                smb + (uint32_t)((warp*16 + lm)*HP + ks*16 + ah8)*2);
            #pragma unroll
            for (int j = 0; j < 4; ++j) {
                uint32_t vf0, vf1, vf2, vf3;
                ldsm_x4_t(vf0, vf1, vf2, vf3,
                    vbase + (uint32_t)((ks*16 + vrow)*HP + j*16 + vcol)*2);
                mma_tf32(accO[2*j],   pf0, pf1, pf2, pf3, vf0, vf1);
                mma_tf32(accO[2*j+1], pf0, pf1, pf2, pf3, vf2, vf3);
            }
        }
    }

    #pragma unroll
    for (int g = 0; g < 2; ++g) {
        float inv = 1.0f / lrow[g];
        int n = q0r + warp*16 + gid + 8*g;
        #pragma unroll
        for (int nt = 0; nt < 8; ++nt) {
            int col = h*64 + nt*8 + 2*tig;
            float2 o;
            o.x = accO[nt][2*g]   * inv;
            o.y = accO[nt][2*g+1] * inv;
            *(float2*)&Og[((size_t)b * Nn + n) * HIDD + col] = o;
        }
    }
}

// ---------------- LayerNorm + exact GELU: single-pass stats, shuffle reductions ----------------
__global__ __launch_bounds__(256) void ln_gelu_kernel(
    const float* __restrict__ H, const float* __restrict__ g,
    const float* __restrict__ bta, float* __restrict__ out)
{
    __shared__ float part[8][2];
    __shared__ float stat[2];
    const size_t rowi = (size_t)blockIdx.y * ROWS + blockIdx.x;
    const float* p = H + rowi * (2*FEAT);
    int t = threadIdx.x;
    int lane = t & 31, warp = t >> 5;
    float4 v = ((const float4*)p)[t];

    float s1 = v.x + v.y + v.z + v.w;
    float s2 = v.x*v.x + v.y*v.y + v.z*v.z + v.w*v.w;
    #pragma unroll
    for (int m = 16; m > 0; m >>= 1) {
        s1 += __shfl_xor_sync(0xffffffffu, s1, m);
        s2 += __shfl_xor_sync(0xffffffffu, s2, m);
    }
    if (lane == 0) { part[warp][0] = s1; part[warp][1] = s2; }
    __syncthreads();
    if (warp == 0) {
        float a = (lane < 8) ? part[lane][0] : 0.f;
        float b = (lane < 8) ? part[lane][1] : 0.f;
        #pragma unroll
        for (int m = 4; m > 0; m >>= 1) {
            a += __shfl_xor_sync(0xffffffffu, a, m);
            b += __shfl_xor_sync(0xffffffffu, b, m);
        }
        if (lane == 0) {
            float mu  = a * (1.0f / (2*FEAT));
            float var = b * (1.0f / (2*FEAT)) - mu*mu;
            stat[0] = mu;
            stat[1] = rsqrtf(var + 1e-5f);
        }
    }
    __syncthreads();
    float mu = stat[0], rs = stat[1];

    int c = t << 2;
    float4 gv = *(const float4*)(g + c);
    float4 bv = *(const float4*)(bta + c);
    float y0 = (v.x - mu) * rs * gv.x + bv.x;
    float y1 = (v.y - mu) * rs * gv.y + bv.y;
    float y2 = (v.z - mu) * rs * gv.z + bv.z;
    float y3 = (v.w - mu) * rs * gv.w + bv.w;

    const float IS2 = 0.70710678118654752f;
    float4 o;
    o.x = 0.5f * y0 * (1.0f + erff(y0 * IS2));
    o.y = 0.5f * y1 * (1.0f + erff(y1 * IS2));
    o.z = 0.5f * y2 * (1.0f + erff(y2 * IS2));
    o.w = 0.5f * y3 * (1.0f + erff(y3 * IS2));
    ((float4*)(out + rowi * (2*FEAT)))[t] = o;
}

extern "C" void kernel_launch(void* const* d_in, const int* in_sizes, int n_in,
                              void* d_out, int out_size)
{
    const float* x0    = (const float*)d_in[0];
    const float* x1    = (const float*)d_in[1];
    const float* enc0  = (const float*)d_in[2];
    const float* enc1  = (const float*)d_in[3];
    const float* Wqkv  = (const float*)d_in[4];
    const float* bqkv  = (const float*)d_in[5];
    const float* Wproj = (const float*)d_in[6];
    const float* bproj = (const float*)d_in[7];
    const float* W1    = (const float*)d_in[8];
    const float* b1    = (const float*)d_in[9];
    const float* ln_g  = (const float*)d_in[10];
    const float* ln_b  = (const float*)d_in[11];
    const float* W2    = (const float*)d_in[12];
    const float* b2    = (const float*)d_in[13];
    float* out = (float*)d_out;

    __half *q, *k, *v;
    float *o, *msg, *hh, *gg;
    float *wqkvT, *wprojT, *w1T, *w2T;
    cudaGetSymbolAddress((void**)&q,   g_q);
    cudaGetSymbolAddress((void**)&k,   g_k);
    cudaGetSymbolAddress((void**)&v,   g_v);
    cudaGetSymbolAddress((void**)&o,   g_o);
    cudaGetSymbolAddress((void**)&msg, g_msg);
    cudaGetSymbolAddress((void**)&hh,  g_h);
    cudaGetSymbolAddress((void**)&gg,  g_g);
    cudaGetSymbolAddress((void**)&wqkvT,  g_wqkvT);
    cudaGetSymbolAddress((void**)&wprojT, g_wprojT);
    cudaGetSymbolAddress((void**)&w1T,    g_w1T);
    cudaGetSymbolAddress((void**)&w2T,    g_w2T);

    cudaFuncSetAttribute(gemm_tf32,
        cudaFuncAttributeMaxDynamicSharedMemorySize, GSM_BYTES);
    cudaFuncSetAttribute(gemm_qkv,
        cudaFuncAttributeMaxDynamicSharedMemorySize, GSM_BYTES);
    cudaFuncSetAttribute(flash_f16,
        cudaFuncAttributeMaxDynamicSharedMemorySize, FLASH_SMEM_B);

    // transpose all 4 weight matrices (qkv permuted) in one launch
    trw_kernel<<<2560, 256>>>(Wqkv, wqkvT, Wproj, wprojT, W1, w1T, W2, w2T);

    const size_t ZH   = (size_t)ROWS*HIDD;
    const size_t Z2F  = (size_t)ROWS*2*FEAT;

    // q/k/v = rope(x @ Wqkv + bqkv), fused epilogue -> half
    gemm_qkv<<<dim3(3*HIDD/128, ROWS/128, 2), 256, GSM_BYTES>>>(
        x0, x1, wqkvT, bqkv, enc0, enc1, q, k, v);

    flash_f16<<<dim3(Nn/128, BH, 2), 256, FLASH_SMEM_B>>>(q, k, v, o);

    // message = O @ Wproj + bproj
    gemm_tf32<<<dim3(HIDD/128, ROWS/128, 2), 256, GSM_BYTES>>>(
        o, o + ZH, HIDD, nullptr, nullptr, 0, 1<<30,
        wprojT, bproj, nullptr, nullptr, 0,
        msg, ZH, HIDD, HIDD);

    // h = concat(x, msg) @ W1 + b1
    gemm_tf32<<<dim3(2*FEAT/128, ROWS/128, 2), 256, GSM_BYTES>>>(
        x0, x1, FEAT, msg, msg + ZH, HIDD, FEAT,
        w1T, b1, nullptr, nullptr, 0,
        hh, Z2F, 2*FEAT, FEAT + HIDD);

    ln_gelu_kernel<<<dim3(ROWS, 2), 256>>>(hh, ln_g, ln_b, gg);

    // out = x + g @ W2 + b2
    gemm_tf32<<<dim3(FEAT/128, ROWS/128, 2), 256, GSM_BYTES>>>(
        gg, gg + Z2F, 2*FEAT, nullptr, nullptr, 0, 1<<30,
        w2T, b2, x0, x1, FEAT,
        out, (size_t)ROWS*FEAT, FEAT, 2*FEAT);
}

// round 17
// speedup vs baseline: 1.7154x; 1.4422x over previous
#include <cuda_runtime.h>
#include <cuda_fp16.h>
#include <math.h>
#include <stdint.h>

#define Bb   4
#define Nn   2048
#define FEAT 512
#define HIDD 512
#define Hh   8
#define HD   64
#define ROWS (Bb*Nn)          // 8192
#define BH   (Bb*Hh)          // 32

// ---------------- scratch ----------------
__device__ __half g_xh[(size_t)2*ROWS*FEAT];  // [z] x in half
__device__ __half g_q[(size_t)2*ROWS*HIDD];   // [z][BH,N,HD], q pre-scaled log2e/8
__device__ __half g_k[(size_t)2*ROWS*HIDD];
__device__ __half g_v[(size_t)2*ROWS*HIDD];
__device__ __half g_o[(size_t)2*ROWS*HIDD];   // [z][B,N,HID] half
__device__ __half g_msg[(size_t)2*ROWS*HIDD];
__device__ float  g_h[(size_t)2*ROWS*2*FEAT]; // LN input fp32
__device__ __half g_g[(size_t)2*ROWS*2*FEAT]; // LN/gelu output half
// transposed weights [N][K] in half (wqkvT rows PERMUTED: j=(c%3)*512+c/3)
__device__ __half g_wqkvT[(size_t)(3*HIDD)*FEAT];
__device__ __half g_wprojT[(size_t)HIDD*HIDD];
__device__ __half g_w1T[(size_t)(2*FEAT)*(FEAT+HIDD)];
__device__ __half g_w2T[(size_t)FEAT*(2*FEAT)];

// ---------------- helpers ----------------
__device__ __forceinline__ uint32_t s2u(const void* p) {
    return (uint32_t)__cvta_generic_to_shared(p);
}
__device__ __forceinline__ void cpa16(uint32_t dst, const void* src) {
    asm volatile("cp.async.cg.shared.global [%0], [%1], 16;\n" :: "r"(dst), "l"(src));
}
__device__ __forceinline__ void cpa_commit() {
    asm volatile("cp.async.commit_group;\n");
}
template<int N> __device__ __forceinline__ void cpa_wait() {
    asm volatile("cp.async.wait_group %0;\n" :: "n"(N));
}
__device__ __forceinline__ void ldsm_x4(uint32_t& r0, uint32_t& r1,
                                        uint32_t& r2, uint32_t& r3, uint32_t addr) {
    asm volatile("ldmatrix.sync.aligned.m8n8.x4.shared.b16 {%0,%1,%2,%3}, [%4];"
        : "=r"(r0), "=r"(r1), "=r"(r2), "=r"(r3) : "r"(addr));
}
__device__ __forceinline__ void ldsm_x4_t(uint32_t& r0, uint32_t& r1,
                                          uint32_t& r2, uint32_t& r3, uint32_t addr) {
    asm volatile("ldmatrix.sync.aligned.m8n8.x4.trans.shared.b16 {%0,%1,%2,%3}, [%4];"
        : "=r"(r0), "=r"(r1), "=r"(r2), "=r"(r3) : "r"(addr));
}
__device__ __forceinline__ float ex2f(float x) {
    float r;
    asm("ex2.approx.f32 %0, %1;" : "=f"(r) : "f"(x));
    return r;
}
__device__ __forceinline__ void mma_f16(float* d,
    uint32_t a0, uint32_t a1, uint32_t a2, uint32_t a3,
    uint32_t b0, uint32_t b1)
{
    asm volatile(
        "mma.sync.aligned.m16n8k16.row.col.f32.f16.f16.f32 "
        "{%0,%1,%2,%3},{%4,%5,%6,%7},{%8,%9},{%0,%1,%2,%3};"
        : "+f"(d[0]), "+f"(d[1]), "+f"(d[2]), "+f"(d[3])
        : "r"(a0), "r"(a1), "r"(a2), "r"(a3), "r"(b0), "r"(b1));
}

// ---------------- x -> half ----------------
__global__ __launch_bounds__(256) void cvt_x(
    const float* __restrict__ x0, const float* __restrict__ x1,
    __half* __restrict__ xh)
{
    size_t i = ((size_t)blockIdx.x * 256 + threadIdx.x) * 8;
    const size_t Z = (size_t)ROWS * FEAT;
    const float* src = (i < Z) ? x0 : x1;
    size_t off = (i < Z) ? i : i - Z;
    float4 a = *(const float4*)(src + off);
    float4 b = *(const float4*)(src + off + 4);
    __half2 h0 = __floats2half2_rn(a.x, a.y);
    __half2 h1 = __floats2half2_rn(a.z, a.w);
    __half2 h2 = __floats2half2_rn(b.x, b.y);
    __half2 h3 = __floats2half2_rn(b.z, b.w);
    __half2* d = (__half2*)(xh + i);
    d[0]=h0; d[1]=h1; d[2]=h2; d[3]=h3;
}

// ---------------- merged weight transpose -> half (qkv rows permuted) ----------------
__global__ __launch_bounds__(256) void trw_kernel(
    const float* __restrict__ s0, __half* __restrict__ d0p,
    const float* __restrict__ s1, __half* __restrict__ d1p,
    const float* __restrict__ s2, __half* __restrict__ d2p,
    const float* __restrict__ s3, __half* __restrict__ d3p)
{
    __shared__ float tile[32][33];
    int tb = blockIdx.x;
    const float* src; __half* dst; int R, C, lt, perm;
    if (tb < 768)       { src=s0; dst=d0p; R=FEAT;      C=3*HIDD; lt=tb;      perm=1; }
    else if (tb < 1024) { src=s1; dst=d1p; R=HIDD;      C=HIDD;   lt=tb-768;  perm=0; }
    else if (tb < 2048) { src=s2; dst=d2p; R=FEAT+HIDD; C=2*FEAT; lt=tb-1024; perm=0; }
    else                { src=s3; dst=d3p; R=2*FEAT;    C=FEAT;   lt=tb-2048; perm=0; }
    int tC = C >> 5;
    int bx = lt % tC, by = lt / tC;

    int tx = threadIdx.x & 31, ty = threadIdx.x >> 5;
    int x = bx*32 + tx;
    #pragma unroll
    for (int i = ty; i < 32; i += 8) {
        int y = by*32 + i;
        tile[i][tx] = src[(size_t)y*C + x];
    }
    __syncthreads();
    int xt = by*32 + tx;
    #pragma unroll
    for (int i = ty; i < 32; i += 8) {
        int c = bx*32 + i;
        int jrow = perm ? ((c % 3)*512 + c/3) : c;
        dst[(size_t)jrow*R + xt] = __float2half_rn(tile[tx][i]);
    }
}

// ---------------- fp16 GEMM (batched z=0,1): C = [A|A2] @ B + bias (+resid) ----------------
// 128x128 tile, K-tile 32 halves, 3-stage cp.async, ldsm A + B^T, m16n8k16.
// smem halves: A [128][40] = 5120, B [128][40] = 5120; stage 10240 halves.
#define HSTG 5120
#define HST_TOT 10240
#define GH_BYTES (3*HST_TOT*2)   // 61440

__global__ __launch_bounds__(256, 2) void gemm_f16(
    const __half* __restrict__ A0, const __half* __restrict__ A1, int lda,
    const __half* __restrict__ A2_0, const __half* __restrict__ A2_1, int lda2, int ksplit,
    const __half* __restrict__ BT,
    const float* __restrict__ bias,
    const float* __restrict__ R0, const float* __restrict__ R1, int ldr,
    float* __restrict__ Cf, __half* __restrict__ Ch, size_t zstrC, int ldc, int K)
{
    extern __shared__ uint32_t gsm[];

    const int z = blockIdx.z;
    const __half* A     = z ? A1   : A0;
    const __half* A2    = z ? A2_1 : A2_0;
    const float*  resid = z ? R1   : R0;

    const int t    = threadIdx.x;
    const int lane = t & 31;
    const int warp = t >> 5;
    const int wm   = warp & 3;
    const int wn   = warp >> 2;
    const int rb   = blockIdx.y * 128;
    const int cb   = blockIdx.x * 128;

    const int arow = t >> 1;
    const int ah   = (t & 1) * 16;     // halves

    const int gid  = lane >> 2;
    const int tig  = lane & 3;

    const int lm   = lane & 15;
    const int ah8  = (lane >> 4) * 8;
    const int brow = (lane >> 4)*8 + (lane & 7);
    const int bcol = ((lane >> 3) & 1) * 8;

    const uint32_t smb = s2u(gsm);

    auto issue_copy = [&](int kt, int s) {
        int kg = (kt << 5) + ah;
        const __half* asrc = (A2 && kg >= ksplit)
            ? A2 + (size_t)(rb + arow) * lda2 + (kg - ksplit)
            : A  + (size_t)(rb + arow) * lda  + kg;
        uint32_t adst = smb + (uint32_t)(s*HST_TOT + arow*40 + ah) * 2;
        cpa16(adst,      asrc);
        cpa16(adst + 16, asrc + 8);
        const __half* bsrc = BT + (size_t)(cb + arow) * K + kg;
        uint32_t bdst = smb + (uint32_t)(s*HST_TOT + HSTG + arow*40 + ah) * 2;
        cpa16(bdst,      bsrc);
        cpa16(bdst + 16, bsrc + 8);
        cpa_commit();
    };

    float acc[2][8][4] = {};

    const int nk = K >> 5;
    issue_copy(0, 0);
    issue_copy(1, 1);

    for (int kt = 0; kt < nk; ++kt) {
        const int s = kt % 3;
        if (kt < nk - 1) cpa_wait<1>(); else cpa_wait<0>();
        __syncthreads();
        if (kt + 2 < nk) issue_copy(kt + 2, (kt + 2) % 3);

        const uint32_t abase = smb + (uint32_t)(s*HST_TOT)*2;
        const uint32_t bbase = abase + HSTG*2;
        #pragma unroll
        for (int ks = 0; ks < 2; ++ks) {
            uint32_t af0[4], af1[4];
            ldsm_x4(af0[0], af0[1], af0[2], af0[3],
                abase + (uint32_t)((wm*32 + lm)*40 + ks*16 + ah8)*2);
            ldsm_x4(af1[0], af1[1], af1[2], af1[3],
                abase + (uint32_t)((wm*32 + 16 + lm)*40 + ks*16 + ah8)*2);
            #pragma unroll
            for (int j = 0; j < 4; ++j) {
                uint32_t r0, r1, r2, r3;
                ldsm_x4(r0, r1, r2, r3,
                    bbase + (uint32_t)((wn*64 + j*16 + brow)*40 + ks*16 + bcol)*2);
                mma_f16(acc[0][2*j],   af0[0], af0[1], af0[2], af0[3], r0, r1);
                mma_f16(acc[1][2*j],   af1[0], af1[1], af1[2], af1[3], r0, r1);
                mma_f16(acc[0][2*j+1], af0[0], af0[1], af0[2], af0[3], r2, r3);
                mma_f16(acc[1][2*j+1], af1[0], af1[1], af1[2], af1[3], r2, r3);
            }
        }
    }

    #pragma unroll
    for (int mt = 0; mt < 2; ++mt) {
        #pragma unroll
        for (int nt = 0; nt < 8; ++nt) {
            int row0 = rb + wm*32 + mt*16 + gid;
            int col  = cb + wn*64 + nt*8 + 2*tig;
            float2 bz = *(const float2*)(bias + col);
            float o00 = acc[mt][nt][0] + bz.x;
            float o01 = acc[mt][nt][1] + bz.y;
            float o10 = acc[mt][nt][2] + bz.x;
            float o11 = acc[mt][nt][3] + bz.y;
            if (Ch != nullptr) {
                __half* Cz = Ch + (size_t)z * zstrC;
                *(__half2*)&Cz[(size_t)row0 * ldc + col]     = __floats2half2_rn(o00, o01);
                *(__half2*)&Cz[(size_t)(row0+8) * ldc + col] = __floats2half2_rn(o10, o11);
            } else {
                if (resid != nullptr) {
                    float2 r0 = *(const float2*)(resid + (size_t)row0 * ldr + col);
                    float2 r1 = *(const float2*)(resid + (size_t)(row0+8) * ldr + col);
                    o00 += r0.x; o01 += r0.y;
                    o10 += r1.x; o11 += r1.y;
                }
                float* Cz = Cf + (size_t)z * zstrC;
                *(float2*)&Cz[(size_t)row0 * ldc + col]     = make_float2(o00, o01);
                *(float2*)&Cz[(size_t)(row0+8) * ldc + col] = make_float2(o10, o11);
            }
        }
    }
}

// ---------------- qkv fp16 GEMM with fused RoPE epilogue ----------------
__global__ __launch_bounds__(256, 2) void gemm_qkv(
    const __half* __restrict__ Xh,
    const __half* __restrict__ BT,
    const float* __restrict__ bias,
    const float* __restrict__ enc0, const float* __restrict__ enc1,
    __half* __restrict__ qb, __half* __restrict__ kb, __half* __restrict__ vb)
{
    extern __shared__ uint32_t gsm[];

    const int z = blockIdx.z;
    const __half* A  = Xh + (size_t)z * ROWS * FEAT;
    const float* enc = z ? enc1 : enc0;
    const size_t zo  = (size_t)z * ROWS * HIDD;

    const int t    = threadIdx.x;
    const int lane = t & 31;
    const int warp = t >> 5;
    const int wm   = warp & 3;
    const int wn   = warp >> 2;
    const int rb   = blockIdx.y * 128;
    const int cb   = blockIdx.x * 128;

    const int arow = t >> 1;
    const int ah   = (t & 1) * 16;

    const int gid  = lane >> 2;
    const int tig  = lane & 3;

    const int lm   = lane & 15;
    const int ah8  = (lane >> 4) * 8;
    const int brow = (lane >> 4)*8 + (lane & 7);
    const int bcol = ((lane >> 3) & 1) * 8;

    const uint32_t smb = s2u(gsm);
    const int K = FEAT;

    auto issue_copy = [&](int kt, int s) {
        int kg = (kt << 5) + ah;
        const __half* asrc = A + (size_t)(rb + arow) * FEAT + kg;
        uint32_t adst = smb + (uint32_t)(s*HST_TOT + arow*40 + ah) * 2;
        cpa16(adst,      asrc);
        cpa16(adst + 16, asrc + 8);
        const __half* bsrc = BT + (size_t)(cb + arow) * K + kg;
        uint32_t bdst = smb + (uint32_t)(s*HST_TOT + HSTG + arow*40 + ah) * 2;
        cpa16(bdst,      bsrc);
        cpa16(bdst + 16, bsrc + 8);
        cpa_commit();
    };

    float acc[2][8][4] = {};

    const int nk = K >> 5;   // 16
    issue_copy(0, 0);
    issue_copy(1, 1);

    for (int kt = 0; kt < nk; ++kt) {
        const int s = kt % 3;
        if (kt < nk - 1) cpa_wait<1>(); else cpa_wait<0>();
        __syncthreads();
        if (kt + 2 < nk) issue_copy(kt + 2, (kt + 2) % 3);

        const uint32_t abase = smb + (uint32_t)(s*HST_TOT)*2;
        const uint32_t bbase = abase + HSTG*2;
        #pragma unroll
        for (int ks = 0; ks < 2; ++ks) {
            uint32_t af0[4], af1[4];
            ldsm_x4(af0[0], af0[1], af0[2], af0[3],
                abase + (uint32_t)((wm*32 + lm)*40 + ks*16 + ah8)*2);
            ldsm_x4(af1[0], af1[1], af1[2], af1[3],
                abase + (uint32_t)((wm*32 + 16 + lm)*40 + ks*16 + ah8)*2);
            #pragma unroll
            for (int j = 0; j < 4; ++j) {
                uint32_t r0, r1, r2, r3;
                ldsm_x4(r0, r1, r2, r3,
                    bbase + (uint32_t)((wn*64 + j*16 + brow)*40 + ks*16 + bcol)*2);
                mma_f16(acc[0][2*j],   af0[0], af0[1], af0[2], af0[3], r0, r1);
                mma_f16(acc[1][2*j],   af1[0], af1[1], af1[2], af1[3], r0, r1);
                mma_f16(acc[0][2*j+1], af0[0], af0[1], af0[2], af0[3], r2, r3);
                mma_f16(acc[1][2*j+1], af1[0], af1[1], af1[2], af1[3], r2, r3);
            }
        }
    }

    // fused RoPE epilogue -> half
    const int sec = cb >> 9;
    const float QS = 0.125f * 1.44269504088896340736f;
    const size_t ESTR = (size_t)Bb * Nn * HD;
    __half* dst = (sec == 0) ? qb : (sec == 1) ? kb : vb;

    #pragma unroll
    for (int mt = 0; mt < 2; ++mt) {
        #pragma unroll
        for (int nt = 0; nt < 8; ++nt) {
            int c    = cb + wn*64 + nt*8 + 2*tig;
            int tcol = c & 511;
            int h    = tcol >> 6;
            int hd   = tcol & 63;
            float bz0 = bias[h*192 + hd*3 + sec];
            float bz1 = bias[h*192 + (hd+1)*3 + sec];
            #pragma unroll
            for (int rr = 0; rr < 2; ++rr) {
                int row = rb + wm*32 + mt*16 + gid + rr*8;
                float v0 = acc[mt][nt][2*rr]   + bz0;
                float v1 = acc[mt][nt][2*rr+1] + bz1;
                float o0, o1;
                if (sec == 2) {
                    o0 = v0; o1 = v1;
                } else {
                    size_t eb = (size_t)row * HD + hd;
                    float f00 = enc[eb], f01 = enc[eb+1];
                    float f10 = enc[ESTR+eb], f11 = enc[ESTR+eb+1];
                    o0 = v0*f00 - v1*f10;
                    o1 = v1*f01 + v0*f11;
                    if (sec == 0) { o0 *= QS; o1 *= QS; }
                }
                int bb = row >> 11, n = row & 2047;
                *(__half2*)&dst[zo + ((size_t)(bb*Hh + h)*Nn + n)*HD + hd] =
                    __floats2half2_rn(o0, o1);
            }
        }
    }
}

// ---------------- fp16 flash attention (R16) ----------------
#define HP 72
#define KOFFW 4608
#define KSTRW 2304
#define VOFFW (KOFFW + 2*KSTRW)
#define VSTRW 2304
#define FLASH_SMEM_B ((VOFFW + 2*VSTRW)*4)   // 55296

__global__ __launch_bounds__(256, 2) void flash_f16(
    const __half* __restrict__ Q, const __half* __restrict__ K,
    const __half* __restrict__ V, __half* __restrict__ O)
{
    extern __shared__ uint32_t smu[];

    const int z  = blockIdx.z;
    const int bh = blockIdx.y;
    const int b  = bh >> 3;
    const int h  = bh & 7;
    const size_t zo = (size_t)z * ROWS * HIDD;
    const __half* Qg = Q + zo + (size_t)bh * Nn * HD;
    const __half* Kg = K + zo + (size_t)bh * Nn * HD;
    const __half* Vg = V + zo + (size_t)bh * Nn * HD;
    __half* Og = O + zo;

    const int t    = threadIdx.x;
    const int lane = t & 31;
    const int warp = t >> 5;
    const int gid  = lane >> 2;
    const int tig  = lane & 3;
    const int q0r  = blockIdx.x * 128;

    const uint32_t smb = s2u(smu);

    const int lm  = lane & 15;
    const int ah8 = (lane >> 4) * 8;
    const int vrow = (lane & 7) + ((lane >> 3) & 1) * 8;
    const int vcol = (lane >> 4) * 8;

    auto stage_k = [&](int j0, int s) {
        #pragma unroll
        for (int i = 0; i < 2; ++i) {
            int idx = t + 256*i;
            int row = idx >> 3, ch = (idx & 7) * 8;
            cpa16(smb + (uint32_t)(KOFFW + s*KSTRW)*4 + (uint32_t)(row*HP + ch)*2,
                  Kg + (size_t)(j0 + row)*HD + ch);
        }
        cpa_commit();
    };
    auto stage_v = [&](int j0, int s) {
        #pragma unroll
        for (int i = 0; i < 2; ++i) {
            int idx = t + 256*i;
            int row = idx >> 3, ch = (idx & 7) * 8;
            cpa16(smb + (uint32_t)(VOFFW + s*VSTRW)*4 + (uint32_t)(row*HP + ch)*2,
                  Vg + (size_t)(j0 + row)*HD + ch);
        }
        cpa_commit();
    };

    #pragma unroll
    for (int i = 0; i < 4; ++i) {
        int idx = t + 256*i;
        int row = idx >> 3, ch = (idx & 7) * 8;
        cpa16(smb + (uint32_t)(row*HP + ch)*2, Qg + (size_t)(q0r + row)*HD + ch);
    }
    cpa_commit();
    stage_k(0, 0);
    stage_v(0, 0);

    cpa_wait<2>();
    __syncthreads();

    uint32_t qf[4][4];
    #pragma unroll
    for (int ks = 0; ks < 4; ++ks)
        ldsm_x4(qf[ks][0], qf[ks][1], qf[ks][2], qf[ks][3],
            smb + (uint32_t)((warp*16 + lm)*HP + ks*16 + ah8)*2);

    float accO[8][4] = {};
    float mrow[2] = {-1e30f, -1e30f};
    float lrow[2] = {0.f, 0.f};

    const int NT = Nn / 64;
    for (int it = 0; it < NT; ++it) {
        const int cur = it & 1;
        cpa_wait<1>();
        __syncthreads();

        if (it + 1 < NT) stage_k((it+1)*64, 1-cur);

        const uint32_t* Kw = smu + KOFFW + cur*KSTRW;
        float s[8][4] = {};
        #pragma unroll
        for (int ks = 0; ks < 4; ++ks) {
            #pragma unroll
            for (int nt = 0; nt < 8; ++nt) {
                int n = nt*8 + gid;
                uint32_t b0 = Kw[n*36 + ks*8 + tig];
                uint32_t b1 = Kw[n*36 + ks*8 + tig + 4];
                mma_f16(s[nt], qf[ks][0], qf[ks][1], qf[ks][2], qf[ks][3], b0, b1);
            }
        }

        #pragma unroll
        for (int g = 0; g < 2; ++g) {
            float tm = -1e30f;
            #pragma unroll
            for (int nt = 0; nt < 8; ++nt)
                tm = fmaxf(tm, fmaxf(s[nt][2*g], s[nt][2*g+1]));
            tm = fmaxf(tm, __shfl_xor_sync(0xffffffffu, tm, 1));
            tm = fmaxf(tm, __shfl_xor_sync(0xffffffffu, tm, 2));
            float mn = fmaxf(mrow[g], tm);
            float alpha = ex2f(mrow[g] - mn);
            mrow[g] = mn;
            float rs = 0.f;
            #pragma unroll
            for (int nt = 0; nt < 8; ++nt) {
                float p0 = ex2f(s[nt][2*g]   - mn);
                float p1 = ex2f(s[nt][2*g+1] - mn);
                s[nt][2*g] = p0; s[nt][2*g+1] = p1;
                rs += p0 + p1;
            }
            rs += __shfl_xor_sync(0xffffffffu, rs, 1);
            rs += __shfl_xor_sync(0xffffffffu, rs, 2);
            lrow[g] = lrow[g]*alpha + rs;
            #pragma unroll
            for (int nt = 0; nt < 8; ++nt) {
                accO[nt][2*g]   *= alpha;
                accO[nt][2*g+1] *= alpha;
            }
        }

        {
            int r0 = warp*16 + gid;
            #pragma unroll
            for (int nt = 0; nt < 8; ++nt) {
                *(__half2*)&smu[r0*36 + nt*4 + tig] =
                    __floats2half2_rn(s[nt][0], s[nt][1]);
                *(__half2*)&smu[(r0+8)*36 + nt*4 + tig] =
                    __floats2half2_rn(s[nt][2], s[nt][3]);
            }
        }
        __syncwarp();

        if (it + 1 < NT) cpa_wait<1>(); else cpa_wait<0>();
        __syncthreads();

        if (it + 1 < NT) stage_v((it+1)*64, 1-cur);

        const uint32_t vbase = smb + (uint32_t)(VOFFW + cur*VSTRW)*4;
        #pragma unroll
        for (int ks = 0; ks < 4; ++ks) {
            uint32_t pf0, pf1, pf2, pf3;
            ldsm_x4(pf0, pf1, pf2, pf3,
                smb + (uint32_t)((warp*16 + lm)*HP + ks*16 + ah8)*2);
            #pragma unroll
            for (int j = 0; j < 4; ++j) {
                uint32_t vf0, vf1, vf2, vf3;
                ldsm_x4_t(vf0, vf1, vf2, vf3,
                    vbase + (uint32_t)((ks*16 + vrow)*HP + j*16 + vcol)*2);
                mma_f16(accO[2*j],   pf0, pf1, pf2, pf3, vf0, vf1);
                mma_f16(accO[2*j+1], pf0, pf1, pf2, pf3, vf2, vf3);
            }
        }
    }

    #pragma unroll
    for (int g = 0; g < 2; ++g) {
        float inv = 1.0f / lrow[g];
        int n = q0r + warp*16 + gid + 8*g;
        #pragma unroll
        for (int nt = 0; nt < 8; ++nt) {
            int col = h*64 + nt*8 + 2*tig;
            *(__half2*)&Og[((size_t)b * Nn + n) * HIDD + col] =
                __floats2half2_rn(accO[nt][2*g] * inv, accO[nt][2*g+1] * inv);
        }
    }
}

// ---------------- LayerNorm + exact GELU -> half ----------------
__global__ __launch_bounds__(256) void ln_gelu_kernel(
    const float* __restrict__ H, const float* __restrict__ g,
    const float* __restrict__ bta, __half* __restrict__ out)
{
    __shared__ float part[8][2];
    __shared__ float stat[2];
    const size_t rowi = (size_t)blockIdx.y * ROWS + blockIdx.x;
    const float* p = H + rowi * (2*FEAT);
    int t = threadIdx.x;
    int lane = t & 31, warp = t >> 5;
    float4 v = ((const float4*)p)[t];

    float s1 = v.x + v.y + v.z + v.w;
    float s2 = v.x*v.x + v.y*v.y + v.z*v.z + v.w*v.w;
    #pragma unroll
    for (int m = 16; m > 0; m >>= 1) {
        s1 += __shfl_xor_sync(0xffffffffu, s1, m);
        s2 += __shfl_xor_sync(0xffffffffu, s2, m);
    }
    if (lane == 0) { part[warp][0] = s1; part[warp][1] = s2; }
    __syncthreads();
    if (warp == 0) {
        float a = (lane < 8) ? part[lane][0] : 0.f;
        float b = (lane < 8) ? part[lane][1] : 0.f;
        #pragma unroll
        for (int m = 4; m > 0; m >>= 1) {
            a += __shfl_xor_sync(0xffffffffu, a, m);
            b += __shfl_xor_sync(0xffffffffu, b, m);
        }
        if (lane == 0) {
            float mu  = a * (1.0f / (2*FEAT));
            float var = b * (1.0f / (2*FEAT)) - mu*mu;
            stat[0] = mu;
            stat[1] = rsqrtf(var + 1e-5f);
        }
    }
    __syncthreads();
    float mu = stat[0], rs = stat[1];

    int c = t << 2;
    float4 gv = *(const float4*)(g + c);
    float4 bv = *(const float4*)(bta + c);
    float y0 = (v.x - mu) * rs * gv.x + bv.x;
    float y1 = (v.y - mu) * rs * gv.y + bv.y;
    float y2 = (v.z - mu) * rs * gv.z + bv.z;
    float y3 = (v.w - mu) * rs * gv.w + bv.w;

    const float IS2 = 0.70710678118654752f;
    float o0 = 0.5f * y0 * (1.0f + erff(y0 * IS2));
    float o1 = 0.5f * y1 * (1.0f + erff(y1 * IS2));
    float o2 = 0.5f * y2 * (1.0f + erff(y2 * IS2));
    float o3 = 0.5f * y3 * (1.0f + erff(y3 * IS2));
    __half2* d = (__half2*)(out + rowi * (2*FEAT) + c);
    d[0] = __floats2half2_rn(o0, o1);
    d[1] = __floats2half2_rn(o2, o3);
}

extern "C" void kernel_launch(void* const* d_in, const int* in_sizes, int n_in,
                              void* d_out, int out_size)
{
    const float* x0    = (const float*)d_in[0];
    const float* x1    = (const float*)d_in[1];
    const float* enc0  = (const float*)d_in[2];
    const float* enc1  = (const float*)d_in[3];
    const float* Wqkv  = (const float*)d_in[4];
    const float* bqkv  = (const float*)d_in[5];
    const float* Wproj = (const float*)d_in[6];
    const float* bproj = (const float*)d_in[7];
    const float* W1    = (const float*)d_in[8];
    const float* b1    = (const float*)d_in[9];
    const float* ln_g  = (const float*)d_in[10];
    const float* ln_b  = (const float*)d_in[11];
    const float* W2    = (const float*)d_in[12];
    const float* b2    = (const float*)d_in[13];
    float* out = (float*)d_out;

    __half *xh, *q, *k, *v, *o, *msg, *gg;
    float *hh;
    __half *wqkvT, *wprojT, *w1T, *w2T;
    cudaGetSymbolAddress((void**)&xh,  g_xh);
    cudaGetSymbolAddress((void**)&q,   g_q);
    cudaGetSymbolAddress((void**)&k,   g_k);
    cudaGetSymbolAddress((void**)&v,   g_v);
    cudaGetSymbolAddress((void**)&o,   g_o);
    cudaGetSymbolAddress((void**)&msg, g_msg);
    cudaGetSymbolAddress((void**)&hh,  g_h);
    cudaGetSymbolAddress((void**)&gg,  g_g);
    cudaGetSymbolAddress((void**)&wqkvT,  g_wqkvT);
    cudaGetSymbolAddress((void**)&wprojT, g_wprojT);
    cudaGetSymbolAddress((void**)&w1T,    g_w1T);
    cudaGetSymbolAddress((void**)&w2T,    g_w2T);

    cudaFuncSetAttribute(gemm_f16,
        cudaFuncAttributeMaxDynamicSharedMemorySize, GH_BYTES);
    cudaFuncSetAttribute(gemm_qkv,
        cudaFuncAttributeMaxDynamicSharedMemorySize, GH_BYTES);
    cudaFuncSetAttribute(flash_f16,
        cudaFuncAttributeMaxDynamicSharedMemorySize, FLASH_SMEM_B);

    // converts (independent; back-to-back)
    cvt_x<<<(2*ROWS*FEAT)/(256*8), 256>>>(x0, x1, xh);
    trw_kernel<<<2560, 256>>>(Wqkv, wqkvT, Wproj, wprojT, W1, w1T, W2, w2T);

    const size_t ZH   = (size_t)ROWS*HIDD;
    const size_t Z2F  = (size_t)ROWS*2*FEAT;

    // q/k/v = rope(xh @ Wqkv + bqkv) -> half
    gemm_qkv<<<dim3(3*HIDD/128, ROWS/128, 2), 256, GH_BYTES>>>(
        xh, wqkvT, bqkv, enc0, enc1, q, k, v);

    flash_f16<<<dim3(Nn/128, BH, 2), 256, FLASH_SMEM_B>>>(q, k, v, o);

    // msg = o @ Wproj + bproj  -> half
    gemm_f16<<<dim3(HIDD/128, ROWS/128, 2), 256, GH_BYTES>>>(
        o, o + ZH, HIDD, nullptr, nullptr, 0, 1<<30,
        wprojT, bproj, nullptr, nullptr, 0,
        nullptr, msg, ZH, HIDD, HIDD);

    // hh = concat(xh, msg) @ W1 + b1  -> fp32
    gemm_f16<<<dim3(2*FEAT/128, ROWS/128, 2), 256, GH_BYTES>>>(
        xh, xh + (size_t)ROWS*FEAT, FEAT, msg, msg + ZH, HIDD, FEAT,
        w1T, b1, nullptr, nullptr, 0,
        hh, nullptr, Z2F, 2*FEAT, FEAT + HIDD);

    ln_gelu_kernel<<<dim3(ROWS, 2), 256>>>(hh, ln_g, ln_b, gg);

    // out = x + gg @ W2 + b2  -> fp32
    gemm_f16<<<dim3(FEAT/128, ROWS/128, 2), 256, GH_BYTES>>>(
        gg, gg + Z2F, 2*FEAT, nullptr, nullptr, 0, 1<<30,
        w2T, b2, x0, x1, FEAT,
        out, nullptr, (size_t)ROWS*FEAT, FEAT, 2*FEAT);
}